// round 12
// baseline (speedup 1.0000x reference)
#include <cuda_runtime.h>
#include <math_constants.h>

#define BB 64
#define CC 256
#define CS 64
#define HW 4096
#define NCL 8

// Scratch (allocation-free rule: __device__ globals)
__device__ float    g_pooled[BB*CC];
__device__ float    g_xmin[BB*CC];
__device__ float    g_xmax[BB*CC];
__device__ float    g_scale[BB*CC];
__device__ unsigned g_cmin_u[NCL];   // order-preserving-encoded cluster min
__device__ unsigned g_cmax_u[NCL];   // order-preserving-encoded cluster max

// Order-preserving float <-> uint encoding (monotone under unsigned compare)
__device__ __forceinline__ unsigned flipf(float f) {
    unsigned u = __float_as_uint(f);
    return (u & 0x80000000u) ? ~u : (u | 0x80000000u);
}
__device__ __forceinline__ float unflipf(unsigned u) {
    u = (u & 0x80000000u) ? (u & 0x7FFFFFFFu) : ~u;
    return __uint_as_float(u);
}

// -------- Kernel 1: per-(b,c) sum/min/max, warp-per-plane (268MB read) -----
__global__ void k1_stats(const float* __restrict__ x) {
    // reset cluster accumulators (k2 gridsyncs on us -> ordered)
    if (blockIdx.x == 0 && threadIdx.x < NCL) {
        g_cmin_u[threadIdx.x] = 0xFFFFFFFFu;   // unsigned-min identity
        g_cmax_u[threadIdx.x] = 0u;            // unsigned-max identity
    }
    int plane = (blockIdx.x * blockDim.x + threadIdx.x) >> 5;  // 0..16383
    int lane  = threadIdx.x & 31;
    const float4* xv = (const float4*)(x + (size_t)plane * HW);
    float s = 0.f, mn = CUDART_INF_F, mx = -CUDART_INF_F;
#pragma unroll 8
    for (int j = 0; j < 32; j++) {
        float4 v = __ldcs(&xv[lane + j * 32]);   // streaming: no reuse
        s += (v.x + v.y) + (v.z + v.w);
        mn = fminf(mn, fminf(fminf(v.x, v.y), fminf(v.z, v.w)));
        mx = fmaxf(mx, fmaxf(fmaxf(v.x, v.y), fmaxf(v.z, v.w)));
    }
#pragma unroll
    for (int o = 16; o > 0; o >>= 1) {
        s  += __shfl_xor_sync(0xFFFFFFFFu, s, o);
        mn  = fminf(mn, __shfl_xor_sync(0xFFFFFFFFu, mn, o));
        mx  = fmaxf(mx, __shfl_xor_sync(0xFFFFFFFFu, mx, o));
    }
    if (lane == 0) {
        g_pooled[plane] = s * (1.0f / HW);
        g_xmin[plane]   = mn;
        g_xmax[plane]   = mx;
    }
    // trigger at END of each block: successor k2 launches into our drain window
    cudaTriggerProgrammaticLaunchCompletion();
}

// -------- Kernel 2: SE MLP; weights prefetched to smem BEFORE gridsync -----
// Dynamic smem: sw1[CS*CC] (w1 as-is) + sw2t[CS*CC] (w2 transposed: [s][c]).
// Weights are kernel inputs (independent of k1) -> safe to load pre-sync;
// total 8MB across 64 blocks, negligible vs k1's 268MB stream.
__global__ void k2_scale(const float* __restrict__ w1, const float* __restrict__ b1,
                         const float* __restrict__ w2, const float* __restrict__ b2,
                         const int* __restrict__ cl) {
    // let k3 launch now; it gridsyncs before doing ANY work (cheap HW sleep)
    cudaTriggerProgrammaticLaunchCompletion();
    extern __shared__ float smw[];
    float* sw1  = smw;                 // [s*CC + c]
    float* sw2t = smw + CS*CC;         // [s*CC + c]  (transposed w2)
    __shared__ float sb1[CS];
    int b = blockIdx.x;       // 0..63
    int t = threadIdx.x;      // 256
    int w = t >> 5, l = t & 31;

    // ---- prefetch weights into smem (overlaps k1's execution) ----
    const float4* w1v = (const float4*)w1;
    float4* sw1v = (float4*)sw1;
#pragma unroll
    for (int i = 0; i < 16; i++)
        sw1v[t + 256*i] = __ldg(&w1v[t + 256*i]);          // 64KB coalesced
    const float4* w2v = (const float4*)w2;
#pragma unroll
    for (int i = 0; i < 16; i++) {
        int idx = t + 256*i;           // float4 index into w2 [c][s]
        float4 vv = __ldg(&w2v[idx]);
        int c = (idx * 4) >> 6;        // row (channel)
        int s = (idx * 4) & 63;        // col (hidden)
        sw2t[(s+0)*CC + c] = vv.x;     // scatter-transpose (latency-tolerant)
        sw2t[(s+1)*CC + c] = vv.y;
        sw2t[(s+2)*CC + c] = vv.z;
        sw2t[(s+3)*CC + c] = vv.w;
    }
    if (t < CS) sb1[t] = __ldg(&b1[t]);
    float bias2 = __ldg(&b2[t]);
    int  c_of_b = __ldg(&cl[b]);
    __syncthreads();                   // smem weights ready

    // ---- wait for k1's outputs ----
    cudaGridDependencySynchronize();

    __shared__ float sp[CC], sh[CS];
    sp[t] = g_pooled[b*CC + t];
    __syncthreads();
#pragma unroll
    for (int i = 0; i < 8; i++) {
        int s = w * 8 + i;
        const float* wr = sw1 + s * CC;
        float acc = 0.0f;
#pragma unroll
        for (int j = 0; j < 8; j++)
            acc = fmaf(sp[l + 32*j], wr[l + 32*j], acc);   // conflict-free LDS
#pragma unroll
        for (int o = 16; o > 0; o >>= 1)
            acc += __shfl_xor_sync(0xFFFFFFFFu, acc, o);
        if (l == 0) sh[s] = fmaxf(acc + sb1[s], 0.0f);     // relu
    }
    __syncthreads();
    float v = bias2;
#pragma unroll 8
    for (int s = 0; s < CS; s++)
        v = fmaf(sh[s], sw2t[s*CC + t], v);                // conflict-free LDS
    float sc = fminf(fmaxf(v / 6.0f + 0.5f, 0.0f), 1.0f);  // hardsigmoid
    g_scale[b*CC + t] = sc;
    // scale >= 0  =>  plane extrema factor through per-(b,c) extrema
    float pm = sc * g_xmin[b*CC + t];
    float pM = sc * g_xmax[b*CC + t];
#pragma unroll
    for (int o = 16; o > 0; o >>= 1) {
        pm = fminf(pm, __shfl_xor_sync(0xFFFFFFFFu, pm, o));
        pM = fmaxf(pM, __shfl_xor_sync(0xFFFFFFFFu, pM, o));
    }
    __shared__ float rmn[8], rmx[8];
    if (l == 0) { rmn[w] = pm; rmx[w] = pM; }
    __syncthreads();
    if (t == 0) {
        float MN = rmn[0], MX = rmx[0];
#pragma unroll
        for (int i = 1; i < 8; i++) { MN = fminf(MN, rmn[i]); MX = fmaxf(MX, rmx[i]); }
        atomicMin(&g_cmin_u[c_of_b], flipf(MN));   // order-independent
        atomicMax(&g_cmax_u[c_of_b], flipf(MX));
    }
}

// -------- Kernel 3: elementwise fake-quant (268MB read + 268MB write) ------
__global__ void k3_quant(const float* __restrict__ x, float* __restrict__ out,
                         const float* __restrict__ act_range,
                         const int* __restrict__ cl) {
    // PDL: wait BEFORE any memory work (R7 showed pre-sync bulk loads steal BW)
    cudaGridDependencySynchronize();
    int bc = blockIdx.x;
    int b  = bc >> 8;
    int t  = threadIdx.x;
    const float4* xv = (const float4*)(x + (size_t)bc * HW);
    float4* ov = (float4*)(out + (size_t)bc * HW);
    float4 v0 = __ldcs(&xv[t]);
    float4 v1 = __ldcs(&xv[t + 256]);
    float4 v2 = __ldcs(&xv[t + 512]);
    float4 v3 = __ldcs(&xv[t + 768]);
    float sc = g_scale[bc];
    __shared__ float sp[3];
    if (t == 0) {
        int c = cl[b];
        float cmin = unflipf(g_cmin_u[c]);
        float cmax = unflipf(g_cmax_u[c]);
        float nmin = act_range[2*c + 0] * 0.995f + cmin * 0.005f;
        float nmax = act_range[2*c + 1] * 0.995f + cmax * 0.005f;
        float s = (nmax - nmin) / 255.0f;
        float z = -rintf(nmin / s);
        sp[0] = s; sp[1] = z; sp[2] = 1.0f / s;
    }
    __syncthreads();
    float ssv = sp[0], zzv = sp[1], inv = sp[2];
    float4 r0, r1, r2, r3;
#define FQ(V, R, F) {                               \
        float o  = sc * V.F;                        \
        float y0 = o * inv;                         \
        float rr = fmaf(-ssv, y0, o);               \
        float y  = fmaf(rr, inv, y0);   /* ~correctly rounded o/ssv */ \
        float q  = rintf(y + zzv);                  \
        q = fminf(fmaxf(q, 0.0f), 255.0f);          \
        R.F = (q - zzv) * ssv; }
#define FQ4(V, R) FQ(V, R, x) FQ(V, R, y) FQ(V, R, z) FQ(V, R, w)
    FQ4(v0, r0) FQ4(v1, r1) FQ4(v2, r2) FQ4(v3, r3)
#undef FQ4
#undef FQ
    __stcs(&ov[t],       r0);
    __stcs(&ov[t + 256], r1);
    __stcs(&ov[t + 512], r2);
    __stcs(&ov[t + 768], r3);
}

extern "C" void kernel_launch(void* const* d_in, const int* in_sizes, int n_in,
                              void* d_out, int out_size) {
    const float* x         = (const float*)d_in[0];
    const float* w1        = (const float*)d_in[1];
    const float* b1        = (const float*)d_in[2];
    const float* w2        = (const float*)d_in[3];
    const float* b2        = (const float*)d_in[4];
    const float* act_range = (const float*)d_in[5];
    const int*   scl       = (const int*)d_in[6];
    float* out = (float*)d_out;

    const int K2_SMEM = 2 * CS * CC * (int)sizeof(float);   // 128 KB
    cudaFuncSetAttribute(k2_scale, cudaFuncAttributeMaxDynamicSharedMemorySize,
                         K2_SMEM);   // idempotent; executes outside capture graph

    k1_stats<<<BB*CC/8, 256>>>(x);                 // 2048 blocks, warp-per-plane

    cudaLaunchAttribute attr[1];
    attr[0].id = cudaLaunchAttributeProgrammaticStreamSerialization;
    attr[0].val.programmaticStreamSerializationAllowed = 1;

    {
        cudaLaunchConfig_t cfg = {};
        cfg.gridDim = dim3(BB);
        cfg.blockDim = dim3(256);
        cfg.dynamicSmemBytes = K2_SMEM;
        cfg.attrs = attr;
        cfg.numAttrs = 1;
        cudaLaunchKernelEx(&cfg, k2_scale, w1, b1, w2, b2, scl);
    }
    {
        cudaLaunchConfig_t cfg = {};
        cfg.gridDim = dim3(BB*CC);
        cfg.blockDim = dim3(256);
        cfg.attrs = attr;
        cfg.numAttrs = 1;
        cudaLaunchKernelEx(&cfg, k3_quant, x, out, act_range, scl);
    }
    (void)in_sizes; (void)n_in; (void)out_size;
}

// round 13
// speedup vs baseline: 1.0861x; 1.0861x over previous
#include <cuda_runtime.h>
#include <math_constants.h>

#define BB 64
#define CC 256
#define CS 64
#define HW 4096
#define NCL 8

// Scratch (allocation-free rule: __device__ globals)
__device__ float    g_pooled[BB*CC];
__device__ float    g_xmin[BB*CC];
__device__ float    g_xmax[BB*CC];
__device__ float    g_scale[BB*CC];
__device__ unsigned g_cmin_u[NCL];   // order-preserving-encoded cluster min
__device__ unsigned g_cmax_u[NCL];   // order-preserving-encoded cluster max

// Order-preserving float <-> uint encoding (monotone under unsigned compare)
__device__ __forceinline__ unsigned flipf(float f) {
    unsigned u = __float_as_uint(f);
    return (u & 0x80000000u) ? ~u : (u | 0x80000000u);
}
__device__ __forceinline__ float unflipf(unsigned u) {
    u = (u & 0x80000000u) ? (u & 0x7FFFFFFFu) : ~u;
    return __uint_as_float(u);
}

// -------- Kernel 1: per-(b,c) sum/min/max, warp-per-plane (268MB read) -----
__global__ void k1_stats(const float* __restrict__ x) {
    // reset cluster accumulators (k2 gridsyncs on us -> ordered)
    if (blockIdx.x == 0 && threadIdx.x < NCL) {
        g_cmin_u[threadIdx.x] = 0xFFFFFFFFu;   // unsigned-min identity
        g_cmax_u[threadIdx.x] = 0u;            // unsigned-max identity
    }
    int plane = (blockIdx.x * blockDim.x + threadIdx.x) >> 5;  // 0..16383
    int lane  = threadIdx.x & 31;
    const float4* xv = (const float4*)(x + (size_t)plane * HW);
    float s = 0.f, mn = CUDART_INF_F, mx = -CUDART_INF_F;
#pragma unroll 8
    for (int j = 0; j < 32; j++) {
        float4 v = __ldcs(&xv[lane + j * 32]);   // streaming: no reuse
        s += (v.x + v.y) + (v.z + v.w);
        mn = fminf(mn, fminf(fminf(v.x, v.y), fminf(v.z, v.w)));
        mx = fmaxf(mx, fmaxf(fmaxf(v.x, v.y), fmaxf(v.z, v.w)));
    }
#pragma unroll
    for (int o = 16; o > 0; o >>= 1) {
        s  += __shfl_xor_sync(0xFFFFFFFFu, s, o);
        mn  = fminf(mn, __shfl_xor_sync(0xFFFFFFFFu, mn, o));
        mx  = fmaxf(mx, __shfl_xor_sync(0xFFFFFFFFu, mx, o));
    }
    if (lane == 0) {
        g_pooled[plane] = s * (1.0f / HW);
        g_xmin[plane]   = mn;
        g_xmax[plane]   = mx;
    }
    // trigger at END of each block: successor k2 launches into our drain window
    cudaTriggerProgrammaticLaunchCompletion();
}

// -------- Kernel 2: SE MLP + hardsigmoid + per-sample min/max -> cluster ---
__global__ void k2_scale(const float* __restrict__ w1, const float* __restrict__ b1,
                         const float* __restrict__ w2, const float* __restrict__ b2,
                         const int* __restrict__ cl) {
    // let k3 launch now; it gridsyncs before doing ANY work (cheap HW sleep)
    cudaTriggerProgrammaticLaunchCompletion();
    int b = blockIdx.x;       // 0..63
    int t = threadIdx.x;      // 256
    int w = t >> 5, l = t & 31;
    // Warm L2 with the weights BEFORE gridsync: inputs are independent of k1,
    // volume is 128KB unique (0.05% of k1's stream) — no register/smem cost.
    {
        const char* p1 = (const char*)w1 + t * 256;        // 64KB, 2 lines/thread
        asm volatile("prefetch.global.L2 [%0];"       :: "l"(p1));
        asm volatile("prefetch.global.L2 [%0 + 128];" :: "l"(p1));
        const char* p2 = (const char*)w2 + t * 256;        // 64KB
        asm volatile("prefetch.global.L2 [%0];"       :: "l"(p2));
        asm volatile("prefetch.global.L2 [%0 + 128];" :: "l"(p2));
    }
    // wait for k1 before touching its outputs
    cudaGridDependencySynchronize();
    __shared__ float sp[CC], sh[CS];
    sp[t] = g_pooled[b*CC + t];
    __syncthreads();
#pragma unroll
    for (int i = 0; i < 8; i++) {
        int s = w * 8 + i;
        const float* wr = w1 + s * CC;
        float acc = 0.0f;
#pragma unroll
        for (int j = 0; j < 8; j++)
            acc = fmaf(sp[l + 32*j], wr[l + 32*j], acc);   // coalesced 128B/iter
#pragma unroll
        for (int o = 16; o > 0; o >>= 1)
            acc += __shfl_xor_sync(0xFFFFFFFFu, acc, o);
        if (l == 0) sh[s] = fmaxf(acc + b1[s], 0.0f);      // relu
    }
    __syncthreads();
    float v = b2[t];
    const float4* w2r = (const float4*)(w2 + t * CS);      // row t contiguous
#pragma unroll
    for (int s4 = 0; s4 < 16; s4++) {
        float4 ww = w2r[s4];
        v = fmaf(sh[4*s4 + 0], ww.x, v);
        v = fmaf(sh[4*s4 + 1], ww.y, v);
        v = fmaf(sh[4*s4 + 2], ww.z, v);
        v = fmaf(sh[4*s4 + 3], ww.w, v);
    }
    float sc = fminf(fmaxf(v / 6.0f + 0.5f, 0.0f), 1.0f);  // hardsigmoid
    g_scale[b*CC + t] = sc;
    // scale >= 0  =>  plane extrema factor through per-(b,c) extrema
    float pm = sc * g_xmin[b*CC + t];
    float pM = sc * g_xmax[b*CC + t];
#pragma unroll
    for (int o = 16; o > 0; o >>= 1) {
        pm = fminf(pm, __shfl_xor_sync(0xFFFFFFFFu, pm, o));
        pM = fmaxf(pM, __shfl_xor_sync(0xFFFFFFFFu, pM, o));
    }
    __shared__ float rmn[8], rmx[8];
    if (l == 0) { rmn[w] = pm; rmx[w] = pM; }
    __syncthreads();
    if (t == 0) {
        float MN = rmn[0], MX = rmx[0];
#pragma unroll
        for (int i = 1; i < 8; i++) { MN = fminf(MN, rmn[i]); MX = fmaxf(MX, rmx[i]); }
        int c = cl[b];
        atomicMin(&g_cmin_u[c], flipf(MN));   // order-independent -> deterministic
        atomicMax(&g_cmax_u[c], flipf(MX));
    }
}

// -------- Kernel 3: elementwise fake-quant (268MB read + 268MB write) ------
__global__ void k3_quant(const float* __restrict__ x, float* __restrict__ out,
                         const float* __restrict__ act_range,
                         const int* __restrict__ cl) {
    // PDL: wait BEFORE any memory work (R7 showed pre-sync bulk loads steal BW)
    cudaGridDependencySynchronize();
    int bc = blockIdx.x;
    int b  = bc >> 8;
    int t  = threadIdx.x;
    const float4* xv = (const float4*)(x + (size_t)bc * HW);
    float4* ov = (float4*)(out + (size_t)bc * HW);
    float4 v0 = __ldcs(&xv[t]);
    float4 v1 = __ldcs(&xv[t + 256]);
    float4 v2 = __ldcs(&xv[t + 512]);
    float4 v3 = __ldcs(&xv[t + 768]);
    float sc = g_scale[bc];
    __shared__ float sp[3];
    if (t == 0) {
        int c = cl[b];
        float cmin = unflipf(g_cmin_u[c]);
        float cmax = unflipf(g_cmax_u[c]);
        float nmin = act_range[2*c + 0] * 0.995f + cmin * 0.005f;
        float nmax = act_range[2*c + 1] * 0.995f + cmax * 0.005f;
        float s = (nmax - nmin) / 255.0f;
        float z = -rintf(nmin / s);
        sp[0] = s; sp[1] = z; sp[2] = 1.0f / s;
    }
    __syncthreads();
    float ssv = sp[0], zzv = sp[1], inv = sp[2];
    float4 r0, r1, r2, r3;
#define FQ(V, R, F) {                               \
        float o  = sc * V.F;                        \
        float y0 = o * inv;                         \
        float rr = fmaf(-ssv, y0, o);               \
        float y  = fmaf(rr, inv, y0);   /* ~correctly rounded o/ssv */ \
        float q  = rintf(y + zzv);                  \
        q = fminf(fmaxf(q, 0.0f), 255.0f);          \
        R.F = (q - zzv) * ssv; }
#define FQ4(V, R) FQ(V, R, x) FQ(V, R, y) FQ(V, R, z) FQ(V, R, w)
    FQ4(v0, r0) FQ4(v1, r1) FQ4(v2, r2) FQ4(v3, r3)
#undef FQ4
#undef FQ
    __stcs(&ov[t],       r0);
    __stcs(&ov[t + 256], r1);
    __stcs(&ov[t + 512], r2);
    __stcs(&ov[t + 768], r3);
}

extern "C" void kernel_launch(void* const* d_in, const int* in_sizes, int n_in,
                              void* d_out, int out_size) {
    const float* x         = (const float*)d_in[0];
    const float* w1        = (const float*)d_in[1];
    const float* b1        = (const float*)d_in[2];
    const float* w2        = (const float*)d_in[3];
    const float* b2        = (const float*)d_in[4];
    const float* act_range = (const float*)d_in[5];
    const int*   scl       = (const int*)d_in[6];
    float* out = (float*)d_out;

    k1_stats<<<BB*CC/8, 256>>>(x);                 // 2048 blocks, warp-per-plane

    cudaLaunchAttribute attr[1];
    attr[0].id = cudaLaunchAttributeProgrammaticStreamSerialization;
    attr[0].val.programmaticStreamSerializationAllowed = 1;

    {
        cudaLaunchConfig_t cfg = {};
        cfg.gridDim = dim3(BB);
        cfg.blockDim = dim3(256);
        cfg.attrs = attr;
        cfg.numAttrs = 1;
        cudaLaunchKernelEx(&cfg, k2_scale, w1, b1, w2, b2, scl);
    }
    {
        cudaLaunchConfig_t cfg = {};
        cfg.gridDim = dim3(BB*CC);
        cfg.blockDim = dim3(256);
        cfg.attrs = attr;
        cfg.numAttrs = 1;
        cudaLaunchKernelEx(&cfg, k3_quant, x, out, act_range, scl);
    }
    (void)in_sizes; (void)n_in; (void)out_size;
}

// round 14
// speedup vs baseline: 1.1561x; 1.0644x over previous
#include <cuda_runtime.h>
#include <math_constants.h>

#define BB 64
#define CC 256
#define CS 64
#define HW 4096
#define NCL 8
#define NPLANE (BB*CC)        // 16384
#define PCUT   10240          // planes >= PCUT cached in L2 by k1 (~96MB tail)

// Scratch (allocation-free rule: __device__ globals)
__device__ float    g_pooled[BB*CC];
__device__ float    g_xmin[BB*CC];
__device__ float    g_xmax[BB*CC];
__device__ float    g_scale[BB*CC];
__device__ unsigned g_cmin_u[NCL];   // order-preserving-encoded cluster min
__device__ unsigned g_cmax_u[NCL];   // order-preserving-encoded cluster max

// Order-preserving float <-> uint encoding (monotone under unsigned compare)
__device__ __forceinline__ unsigned flipf(float f) {
    unsigned u = __float_as_uint(f);
    return (u & 0x80000000u) ? ~u : (u | 0x80000000u);
}
__device__ __forceinline__ float unflipf(unsigned u) {
    u = (u & 0x80000000u) ? (u & 0x7FFFFFFFu) : ~u;
    return __uint_as_float(u);
}

// -------- Kernel 1: per-(b,c) sum/min/max, warp-per-plane (268MB read) -----
// Planes < PCUT: streaming loads (evict-first). Planes >= PCUT: default policy
// so the ~96MB tail stays L2-resident for k3 (which reads in reverse order).
__global__ void k1_stats(const float* __restrict__ x) {
    // reset cluster accumulators (k2 gridsyncs on us -> ordered)
    if (blockIdx.x == 0 && threadIdx.x < NCL) {
        g_cmin_u[threadIdx.x] = 0xFFFFFFFFu;   // unsigned-min identity
        g_cmax_u[threadIdx.x] = 0u;            // unsigned-max identity
    }
    int plane = (blockIdx.x * blockDim.x + threadIdx.x) >> 5;  // 0..16383
    int lane  = threadIdx.x & 31;
    const float4* xv = (const float4*)(x + (size_t)plane * HW);
    float s = 0.f, mn = CUDART_INF_F, mx = -CUDART_INF_F;
#define K1_BODY(LOADV)                                              \
    _Pragma("unroll 8")                                             \
    for (int j = 0; j < 32; j++) {                                  \
        float4 v = LOADV;                                           \
        s += (v.x + v.y) + (v.z + v.w);                             \
        mn = fminf(mn, fminf(fminf(v.x, v.y), fminf(v.z, v.w)));    \
        mx = fmaxf(mx, fmaxf(fmaxf(v.x, v.y), fmaxf(v.z, v.w)));    \
    }
    if (plane < PCUT) {
        K1_BODY(__ldcs(&xv[lane + j * 32]))        // streaming: no reuse
    } else {
        K1_BODY(__ldg(&xv[lane + j * 32]))         // cache: k3 reuses soon
    }
#undef K1_BODY
#pragma unroll
    for (int o = 16; o > 0; o >>= 1) {
        s  += __shfl_xor_sync(0xFFFFFFFFu, s, o);
        mn  = fminf(mn, __shfl_xor_sync(0xFFFFFFFFu, mn, o));
        mx  = fmaxf(mx, __shfl_xor_sync(0xFFFFFFFFu, mx, o));
    }
    if (lane == 0) {
        g_pooled[plane] = s * (1.0f / HW);
        g_xmin[plane]   = mn;
        g_xmax[plane]   = mx;
    }
    // trigger at END of each block: successor k2 launches into our drain window
    cudaTriggerProgrammaticLaunchCompletion();
}

// -------- Kernel 2: SE MLP + hardsigmoid + per-sample min/max -> cluster ---
__global__ void k2_scale(const float* __restrict__ w1, const float* __restrict__ b1,
                         const float* __restrict__ w2, const float* __restrict__ b2,
                         const int* __restrict__ cl) {
    // let k3 launch now; it gridsyncs before doing ANY work (cheap HW sleep)
    cudaTriggerProgrammaticLaunchCompletion();
    int b = blockIdx.x;       // 0..63
    int t = threadIdx.x;      // 256
    int w = t >> 5, l = t & 31;
    // wait for k1 before touching its outputs
    cudaGridDependencySynchronize();
    __shared__ float sp[CC], sh[CS];
    sp[t] = g_pooled[b*CC + t];
    __syncthreads();
#pragma unroll
    for (int i = 0; i < 8; i++) {
        int s = w * 8 + i;
        const float* wr = w1 + s * CC;
        float acc = 0.0f;
#pragma unroll
        for (int j = 0; j < 8; j++)
            acc = fmaf(sp[l + 32*j], wr[l + 32*j], acc);   // coalesced 128B/iter
#pragma unroll
        for (int o = 16; o > 0; o >>= 1)
            acc += __shfl_xor_sync(0xFFFFFFFFu, acc, o);
        if (l == 0) sh[s] = fmaxf(acc + b1[s], 0.0f);      // relu
    }
    __syncthreads();
    float v = b2[t];
    const float4* w2r = (const float4*)(w2 + t * CS);      // row t contiguous
#pragma unroll
    for (int s4 = 0; s4 < 16; s4++) {
        float4 ww = w2r[s4];
        v = fmaf(sh[4*s4 + 0], ww.x, v);
        v = fmaf(sh[4*s4 + 1], ww.y, v);
        v = fmaf(sh[4*s4 + 2], ww.z, v);
        v = fmaf(sh[4*s4 + 3], ww.w, v);
    }
    float sc = fminf(fmaxf(v / 6.0f + 0.5f, 0.0f), 1.0f);  // hardsigmoid
    g_scale[b*CC + t] = sc;
    // scale >= 0  =>  plane extrema factor through per-(b,c) extrema
    float pm = sc * g_xmin[b*CC + t];
    float pM = sc * g_xmax[b*CC + t];
#pragma unroll
    for (int o = 16; o > 0; o >>= 1) {
        pm = fminf(pm, __shfl_xor_sync(0xFFFFFFFFu, pm, o));
        pM = fmaxf(pM, __shfl_xor_sync(0xFFFFFFFFu, pM, o));
    }
    __shared__ float rmn[8], rmx[8];
    if (l == 0) { rmn[w] = pm; rmx[w] = pM; }
    __syncthreads();
    if (t == 0) {
        float MN = rmn[0], MX = rmx[0];
#pragma unroll
        for (int i = 1; i < 8; i++) { MN = fminf(MN, rmn[i]); MX = fmaxf(MX, rmx[i]); }
        int c = cl[b];
        atomicMin(&g_cmin_u[c], flipf(MN));   // order-independent -> deterministic
        atomicMax(&g_cmax_u[c], flipf(MX));
    }
}

// -------- Kernel 3: elementwise fake-quant (268MB read + 268MB write) ------
// Processes planes in REVERSE so its first blocks hit k1's L2-resident tail.
__global__ void k3_quant(const float* __restrict__ x, float* __restrict__ out,
                         const float* __restrict__ act_range,
                         const int* __restrict__ cl) {
    // PDL: wait BEFORE any memory work (R7 showed pre-sync bulk loads steal BW)
    cudaGridDependencySynchronize();
    int bc = (NPLANE - 1) - blockIdx.x;    // reverse: hot L2 tail first
    int b  = bc >> 8;
    int t  = threadIdx.x;
    const float4* xv = (const float4*)(x + (size_t)bc * HW);
    float4* ov = (float4*)(out + (size_t)bc * HW);
    float4 v0 = __ldcs(&xv[t]);
    float4 v1 = __ldcs(&xv[t + 256]);
    float4 v2 = __ldcs(&xv[t + 512]);
    float4 v3 = __ldcs(&xv[t + 768]);
    float sc = g_scale[bc];
    __shared__ float sp[3];
    if (t == 0) {
        int c = cl[b];
        float cmin = unflipf(g_cmin_u[c]);
        float cmax = unflipf(g_cmax_u[c]);
        float nmin = act_range[2*c + 0] * 0.995f + cmin * 0.005f;
        float nmax = act_range[2*c + 1] * 0.995f + cmax * 0.005f;
        float s = (nmax - nmin) / 255.0f;
        float z = -rintf(nmin / s);
        sp[0] = s; sp[1] = z; sp[2] = 1.0f / s;
    }
    __syncthreads();
    float ssv = sp[0], zzv = sp[1], inv = sp[2];
    float4 r0, r1, r2, r3;
#define FQ(V, R, F) {                               \
        float o  = sc * V.F;                        \
        float y0 = o * inv;                         \
        float rr = fmaf(-ssv, y0, o);               \
        float y  = fmaf(rr, inv, y0);   /* ~correctly rounded o/ssv */ \
        float q  = rintf(y + zzv);                  \
        q = fminf(fmaxf(q, 0.0f), 255.0f);          \
        R.F = (q - zzv) * ssv; }
#define FQ4(V, R) FQ(V, R, x) FQ(V, R, y) FQ(V, R, z) FQ(V, R, w)
    FQ4(v0, r0) FQ4(v1, r1) FQ4(v2, r2) FQ4(v3, r3)
#undef FQ4
#undef FQ
    __stcs(&ov[t],       r0);
    __stcs(&ov[t + 256], r1);
    __stcs(&ov[t + 512], r2);
    __stcs(&ov[t + 768], r3);
}

extern "C" void kernel_launch(void* const* d_in, const int* in_sizes, int n_in,
                              void* d_out, int out_size) {
    const float* x         = (const float*)d_in[0];
    const float* w1        = (const float*)d_in[1];
    const float* b1        = (const float*)d_in[2];
    const float* w2        = (const float*)d_in[3];
    const float* b2        = (const float*)d_in[4];
    const float* act_range = (const float*)d_in[5];
    const int*   scl       = (const int*)d_in[6];
    float* out = (float*)d_out;

    k1_stats<<<NPLANE/8, 256>>>(x);                // 2048 blocks, warp-per-plane

    cudaLaunchAttribute attr[1];
    attr[0].id = cudaLaunchAttributeProgrammaticStreamSerialization;
    attr[0].val.programmaticStreamSerializationAllowed = 1;

    {
        cudaLaunchConfig_t cfg = {};
        cfg.gridDim = dim3(BB);
        cfg.blockDim = dim3(256);
        cfg.attrs = attr;
        cfg.numAttrs = 1;
        cudaLaunchKernelEx(&cfg, k2_scale, w1, b1, w2, b2, scl);
    }
    {
        cudaLaunchConfig_t cfg = {};
        cfg.gridDim = dim3(NPLANE);
        cfg.blockDim = dim3(256);
        cfg.attrs = attr;
        cfg.numAttrs = 1;
        cudaLaunchKernelEx(&cfg, k3_quant, x, out, act_range, scl);
    }
    (void)in_sizes; (void)n_in; (void)out_size;
}